// round 9
// baseline (speedup 1.0000x reference)
#include <cuda_runtime.h>

#define NGR  64
#define NN   2048
#define EPG  16384          // edges per graph
#define KK   410
#define HH   3
#define CC   20
#define T    512
#define LEND 0xFFFF         // chain terminator

// ---------------- dynamic smem layout (bytes) -------------------------------
// Region A: hh1/x1 rows of 12 floats (98304 B) -> later hG rows of 64 (104960 B)
#define SZ_A     104960
#define O_LNK    SZ_A                   // u32[16384] packed (src<<16)|next
#define O_HEAD   (O_LNK + 65536)        // int[2048] chain heads
#define O_ENC    (O_HEAD + 8192)        // u32[2048] encoded scores
#define O_DINV   (O_ENC + 8192)         // float[2048]
#define O_HSS    (O_DINV + 8192)        // hss; radix bins; als+perm (P8+)
#define O_SCORE  (O_HSS + 8192)         // score; ald (P8+)
#define O_NEW    (O_SCORE + 8192)       // newidx; readout temps at end
#define SMEM_TOTAL (O_NEW + 8192)

// sub-offsets
#define O_ALS    O_HSS                  // float[410*3]
#define O_PERM   (O_HSS + 4920)         // int[410]
#define O_PART   O_NEW                  // float[8*60]  (after s_new is dead)
#define O_GSUM   (O_NEW + 1920)         // float[60]
#define O_HB     (O_NEW + 2176)         // float[30]
#define O_ZB     (O_NEW + 2304)         // float[3]

__device__ __forceinline__ float lrelu(float x) { return x > 0.f ? x : 0.2f * x; }
__device__ __forceinline__ unsigned encf(float f) {
    unsigned u = __float_as_uint(f);
    return (u & 0x80000000u) ? ~u : (u | 0x80000000u);
}

// block-wide exclusive scan of per-thread sums (all 512 threads must call)
__device__ __forceinline__ int scan_ex(int s, int t, int* wsum) {
    __syncthreads();
    int lane = t & 31, wid = t >> 5;
    int x = s;
#pragma unroll
    for (int d = 1; d < 32; d <<= 1) {
        int y = __shfl_up_sync(0xFFFFFFFFu, x, d);
        if (lane >= d) x += y;
    }
    if (lane == 31) wsum[wid] = x;
    __syncthreads();
    if (t == 0) {
        int run = 0;
#pragma unroll
        for (int w = 0; w < 16; w++) { int tmp = wsum[w]; wsum[w] = run; run += tmp; }
    }
    __syncthreads();
    return wsum[wid] + x - s;
}

__global__ void __launch_bounds__(T, 1)
k_mega(const float* __restrict__ x,
       const int* __restrict__ src, const int* __restrict__ dst,
       const float* __restrict__ W1, const float* __restrict__ b1,
       const float* __restrict__ Ws, const float* __restrict__ bs,
       const float* __restrict__ Wg,
       const float* __restrict__ a_src, const float* __restrict__ a_dst,
       const float* __restrict__ bg,
       const float* __restrict__ Wf1, const float* __restrict__ bf1,
       const float* __restrict__ Wf2, const float* __restrict__ bf2,
       float* __restrict__ out)
{
    extern __shared__ char sm[];
    float*    s_hx   = (float*)(sm);                 // rows of 12
    float*    s_hG   = (float*)(sm);                 // rows of 64 (late)
    unsigned* s_lnk  = (unsigned*)(sm + O_LNK);
    int*      s_head = (int*)(sm + O_HEAD);
    unsigned* s_enc  = (unsigned*)(sm + O_ENC);
    float*    s_dinv = (float*)(sm + O_DINV);
    float*    s_hss  = (float*)(sm + O_HSS);
    int*      s_bins = (int*)(sm + O_HSS);           // radix bins (256)
    float*    s_als  = (float*)(sm + O_ALS);         // P8+
    int*      s_perm = (int*)(sm + O_PERM);          // P8+
    float*    s_scr  = (float*)(sm + O_SCORE);
    float*    s_ald  = (float*)(sm + O_SCORE);       // P8+
    int*      s_new  = (int*)(sm + O_NEW);
    float*    s_part = (float*)(sm + O_PART);
    float*    s_gsum = (float*)(sm + O_GSUM);
    float*    s_hb   = (float*)(sm + O_HB);
    float*    s_zb   = (float*)(sm + O_ZB);

    __shared__ float W1s[50], Wss[10], b1s[10], Wgs[600], asr[60], ads[60];
    __shared__ int wsum[16];
    __shared__ unsigned sPrefix;
    __shared__ int sNeed, sDig, sRem;

    const int g = blockIdx.x;
    const int t = threadIdx.x;
    const int ebase = g * EPG;
    const int nbase = g * NN;
    const float bs0 = bs[0];

    // ---- P0: init heads + weight staging ----
    for (int i = t; i < NN; i += T) s_head[i] = LEND;
    if (t < 50) W1s[t] = W1[t];
    if (t < 10) { Wss[t] = Ws[t]; b1s[t] = b1[t]; }
    for (int k = t; k < 600; k += T) Wgs[k] = Wg[k];
    if (t < 60) { asr[t] = a_src[t]; ads[t] = a_dst[t]; }
    __syncthreads();

    // ---- P1: linked-chain adjacency build (ONE atomic per edge) ----
    for (int eb = t * 4; eb < EPG; eb += T * 4) {
        int4 d4 = *(const int4*)&dst[ebase + eb];
        int4 s4 = *(const int4*)&src[ebase + eb];
        int dd[4] = {d4.x & (NN - 1), d4.y & (NN - 1), d4.z & (NN - 1), d4.w & (NN - 1)};
        int ss[4] = {s4.x & (NN - 1), s4.y & (NN - 1), s4.z & (NN - 1), s4.w & (NN - 1)};
#pragma unroll
        for (int q = 0; q < 4; q++) {
            int old = atomicExch(&s_head[dd[q]], eb + q);
            s_lnk[eb + q] = ((unsigned)ss[q] << 16) | (unsigned)(old & 0xFFFF);
        }
    }
    __syncthreads();

    // ---- P2: degree via chain count + dinv + hh1 = (x@W1)*dinv ----
    for (int i = t; i < NN; i += T) {
        int deg = 0;
        int p = s_head[i];
        while (p != LEND) { deg++; p = (int)(s_lnk[p] & 0xFFFFu); }
        float dv = rsqrtf((float)deg + 1.0f);
        s_dinv[i] = dv;
        float xi[5];
#pragma unroll
        for (int c = 0; c < 5; c++) xi[c] = x[(nbase + i) * 5 + c];
        float h[12];
#pragma unroll
        for (int k = 0; k < 10; k++) {
            float v = 0.f;
#pragma unroll
            for (int c = 0; c < 5; c++) v += xi[c] * W1s[c * 10 + k];
            h[k] = v * dv;
        }
        h[10] = 0.f; h[11] = 0.f;
        float4* o = (float4*)&s_hx[i * 12];
        o[0] = make_float4(h[0], h[1], h[2], h[3]);
        o[1] = make_float4(h[4], h[5], h[6], h[7]);
        o[2] = make_float4(h[8], h[9], h[10], h[11]);
    }
    __syncthreads();

    // ---- P5: GCN1 gather (chain walk, float4) -> x1 in place + scorer hss ----
    {
        float4 a[4][3];
#pragma unroll
        for (int q = 0; q < 4; q++) {
            int i = t + q * T;
            const float4* me = (const float4*)&s_hx[i * 12];
            a[q][0] = me[0]; a[q][1] = me[1]; a[q][2] = me[2];
            int p = s_head[i];
            while (p != LEND) {
                unsigned w = s_lnk[p];
                int s = (int)(w >> 16);
                p = (int)(w & 0xFFFFu);
                const float4* r = (const float4*)&s_hx[s * 12];
                float4 r0 = r[0], r1 = r[1], r2 = r[2];
                a[q][0].x += r0.x; a[q][0].y += r0.y; a[q][0].z += r0.z; a[q][0].w += r0.w;
                a[q][1].x += r1.x; a[q][1].y += r1.y; a[q][1].z += r1.z; a[q][1].w += r1.w;
                a[q][2].x += r2.x; a[q][2].y += r2.y;
            }
        }
        __syncthreads();
#pragma unroll
        for (int q = 0; q < 4; q++) {
            int i = t + q * T;
            float dv = s_dinv[i];
            float v[10] = {a[q][0].x, a[q][0].y, a[q][0].z, a[q][0].w,
                           a[q][1].x, a[q][1].y, a[q][1].z, a[q][1].w,
                           a[q][2].x, a[q][2].y};
            float hs = 0.f;
#pragma unroll
            for (int k = 0; k < 10; k++) {
                v[k] = v[k] * dv + b1s[k];
                hs += v[k] * Wss[k];
            }
            float4* o = (float4*)&s_hx[i * 12];
            o[0] = make_float4(v[0], v[1], v[2], v[3]);
            o[1] = make_float4(v[4], v[5], v[6], v[7]);
            o[2] = make_float4(v[8], v[9], 0.f, 0.f);
            s_hss[i] = hs * dv;
        }
    }
    __syncthreads();

    // ---- P6: scorer gather (chain walk) -> score + enc ----
    for (int i = t; i < NN; i += T) {
        float sc = s_hss[i];
        int p = s_head[i];
        while (p != LEND) {
            unsigned w = s_lnk[p];
            sc += s_hss[w >> 16];
            p = (int)(w & 0xFFFFu);
        }
        sc = sc * s_dinv[i] + bs0;
        s_scr[i] = sc;
        s_enc[i] = encf(sc);
    }
    __syncthreads();

    // ---- P7: top-K via 8-bit radix select on enc (descending), then compact --
    {
        if (t == 0) { sPrefix = 0u; sNeed = KK; }
        __syncthreads();
        int i0 = t * 4;
#pragma unroll
        for (int shift = 24; shift >= 0; shift -= 8) {
            if (t < 256) s_bins[t] = 0;
            __syncthreads();
            unsigned pfx = sPrefix;
#pragma unroll
            for (int q = 0; q < 4; q++) {
                unsigned e = s_enc[i0 + q];
                bool match = (shift == 24) || ((e >> (shift + 8)) == pfx);
                if (match) atomicAdd(&s_bins[(e >> shift) & 255], 1);
            }
            __syncthreads();
            int mycount = (t < 256) ? s_bins[255 - t] : 0;
            int ex = scan_ex(mycount, t, wsum);
            if (t < 256) {
                int need = sNeed;
                if (ex < need && need <= ex + mycount) {
                    sDig = 255 - t;
                    sRem = need - ex;
                }
            }
            __syncthreads();
            if (t == 0) { sPrefix = (sPrefix << 8) | (unsigned)sDig; sNeed = sRem; }
            __syncthreads();
        }
        unsigned KT = sPrefix;   // KK-th largest enc (tie value)
        int tneed = sNeed;       // ties to accept (smallest index first)
        int ng = KK - tneed;
        int pg[4], pt[4];
#pragma unroll
        for (int q = 0; q < 4; q++) {
            unsigned e = s_enc[i0 + q];
            pg[q] = (e > KT) ? 1 : 0;
            pt[q] = (e == KT) ? 1 : 0;
        }
        int exg = scan_ex(pg[0] + pg[1] + pg[2] + pg[3], t, wsum);
        int ext = scan_ex(pt[0] + pt[1] + pt[2] + pt[3], t, wsum);
#pragma unroll
        for (int q = 0; q < 4; q++) {
            int i = i0 + q;
            int slot = -1;
            if (pg[q]) slot = exg;
            else if (pt[q] && ext < tneed) slot = ng + ext;
            if (slot >= 0) { s_perm[slot] = i; s_new[i] = slot; }
            else s_new[i] = -1;
            exg += pg[q];
            ext += pt[q];
        }
    }
    __syncthreads();

    // ---- P8: pooled precompute: hG = (x1*tanh(score)) @ Wg ; als/ald ----
    float hg[60], als3[3], ald3[3];
    int node = -1;
    if (t < KK) {
        node = s_perm[t];
        float gate = tanhf(s_scr[node]);
        float xp[10];
#pragma unroll
        for (int c = 0; c < 10; c++) xp[c] = s_hx[node * 12 + c] * gate;
#pragma unroll
        for (int h = 0; h < HH; h++) { als3[h] = 0.f; ald3[h] = 0.f; }
#pragma unroll
        for (int h = 0; h < HH; h++) {
#pragma unroll
            for (int c = 0; c < CC; c++) {
                int k = h * CC + c;
                float v = 0.f;
#pragma unroll
                for (int q = 0; q < 10; q++) v += xp[q] * Wgs[q * 60 + k];
                hg[k] = v;
                als3[h] += v * asr[k];
                ald3[h] += v * ads[k];
            }
        }
    }
    __syncthreads();   // all reads of s_hx/s_scr done
    if (t < KK) {
#pragma unroll
        for (int k = 0; k < 60; k++) s_hG[t * 64 + k] = hg[k];
#pragma unroll
        for (int h = 0; h < HH; h++) {
            s_als[t * 3 + h] = als3[h];
            s_ald[t * 3 + h] = ald3[h];
        }
    }
    __syncthreads();

    // ---- P9: GAT softmax-aggregate (logits ~1e-2: exp w/o max-sub exact) ----
    float4 oa[15];
    if (t < KK) {
        float den[3];
#pragma unroll
        for (int h = 0; h < HH; h++)
            den[h] = __expf(lrelu(s_als[t * 3 + h] + s_ald[t * 3 + h]));
        const float4* self = (const float4*)&s_hG[t * 64];
#pragma unroll
        for (int k = 0; k < 15; k++) {
            float w = den[k / 5];
            float4 v = self[k];
            oa[k] = make_float4(v.x * w, v.y * w, v.z * w, v.w * w);
        }
        float aldj0 = s_ald[t * 3 + 0], aldj1 = s_ald[t * 3 + 1], aldj2 = s_ald[t * 3 + 2];
        int p = s_head[node];
        while (p != LEND) {
            unsigned w = s_lnk[p];
            int sj = s_new[w >> 16];
            p = (int)(w & 0xFFFFu);
            if (sj < 0) continue;
            float w0 = __expf(lrelu(s_als[sj * 3 + 0] + aldj0));
            float w1 = __expf(lrelu(s_als[sj * 3 + 1] + aldj1));
            float w2 = __expf(lrelu(s_als[sj * 3 + 2] + aldj2));
            den[0] += w0; den[1] += w1; den[2] += w2;
            const float4* row = (const float4*)&s_hG[sj * 64];
#pragma unroll
            for (int k = 0; k < 15; k++) {
                float ww = (k < 5) ? w0 : (k < 10 ? w1 : w2);
                float4 v = row[k];
                oa[k].x += v.x * ww; oa[k].y += v.y * ww;
                oa[k].z += v.z * ww; oa[k].w += v.w * ww;
            }
        }
        float iv[3] = {1.f / den[0], 1.f / den[1], 1.f / den[2]};
#pragma unroll
        for (int k = 0; k < 15; k++) {
            float w = iv[k / 5];
            oa[k].x *= w; oa[k].y *= w; oa[k].z *= w; oa[k].w *= w;
        }
    }
    __syncthreads();   // all reads of s_hG done
    if (t < KK) {
        float4* o = (float4*)&s_hG[t * 64];
#pragma unroll
        for (int k = 0; k < 15; k++) o[k] = oa[k];
    }
    __syncthreads();

    // ---- readout reduction over 410 rows ----
    {
        int col = t & 63, grp = t >> 6;
        if (col < 60) {
            float a = 0.f;
            for (int r = grp; r < KK; r += 8) a += s_hG[r * 64 + col];
            s_part[grp * 60 + col] = a;
        }
    }
    __syncthreads();
    if (t < 60) {
        float a = 0.f;
#pragma unroll
        for (int q = 0; q < 8; q++) a += s_part[q * 60 + t];
        s_gsum[t] = a + (float)KK * bg[t];
    }
    __syncthreads();

    // ---- MLP + log_softmax ----
    if (t < 30) {
        float v = bf1[t];
#pragma unroll
        for (int c = 0; c < 60; c++) v += s_gsum[c] * Wf1[c * 30 + t];
        s_hb[t] = v > 0.f ? v : 0.f;
    }
    __syncthreads();
    if (t < 3) {
        float v = bf2[t];
#pragma unroll
        for (int c = 0; c < 30; c++) v += s_hb[c] * Wf2[c * 3 + t];
        s_zb[t] = v;
    }
    __syncthreads();
    if (t == 0) {
        float m = fmaxf(s_zb[0], fmaxf(s_zb[1], s_zb[2]));
        float lse = logf(expf(s_zb[0] - m) + expf(s_zb[1] - m) + expf(s_zb[2] - m)) + m;
        out[g * 3 + 0] = s_zb[0] - lse;
        out[g * 3 + 1] = s_zb[1] - lse;
        out[g * 3 + 2] = s_zb[2] - lse;
    }
}

// ---------------- launch -----------------------------------------------------
extern "C" void kernel_launch(void* const* d_in, const int* in_sizes, int n_in,
                              void* d_out, int out_size) {
    const float* x     = (const float*)d_in[0];
    const int*   src   = (const int*)d_in[1];
    const int*   dst   = (const int*)d_in[2];
    const float* W1    = (const float*)d_in[4];
    const float* b1    = (const float*)d_in[5];
    const float* Ws    = (const float*)d_in[6];
    const float* bs    = (const float*)d_in[7];
    const float* Wg    = (const float*)d_in[8];
    const float* a_src = (const float*)d_in[9];
    const float* a_dst = (const float*)d_in[10];
    const float* bg    = (const float*)d_in[11];
    const float* Wf1   = (const float*)d_in[12];
    const float* bf1   = (const float*)d_in[13];
    const float* Wf2   = (const float*)d_in[14];
    const float* bf2   = (const float*)d_in[15];
    float* out = (float*)d_out;

    static int attr_set = 0;
    if (!attr_set) {
        cudaFuncSetAttribute(k_mega, cudaFuncAttributeMaxDynamicSharedMemorySize,
                             SMEM_TOTAL);
        attr_set = 1;
    }
    k_mega<<<NGR, T, SMEM_TOTAL>>>(x, src, dst, W1, b1, Ws, bs, Wg, a_src, a_dst,
                                   bg, Wf1, bf1, Wf2, bf2, out);
}

// round 10
// speedup vs baseline: 1.0853x; 1.0853x over previous
#include <cuda_runtime.h>

#define NGR  64
#define NN   2048
#define EPG  16384          // edges per graph
#define KK   410
#define HH   3
#define CC   20
#define T    1024
#define NW   (T / 32)

// ---------------- dynamic smem layout (bytes) -------------------------------
// Region A: hh1/x1 rows of 12 floats (98304 B) -> later hG rows of 64 (104960 B)
#define SZ_A     104960
#define O_CSR    SZ_A                   // int[16384]
#define O_CNT    (O_CSR + 65536)        // int[2048]
#define O_OFF    (O_CNT + 8192)         // int[2048]
#define O_CUR    (O_OFF + 8192)         // cursors (P3); enc u32[2048] (P6+)
#define O_DINV   (O_CUR + 8192)         // float[2048]
#define O_HSS    (O_DINV + 8192)        // hss; radix bins; als+perm (P8+)
#define O_SCORE  (O_HSS + 8192)         // score; ald (P8+)
#define O_NEW    (O_SCORE + 8192)       // newidx; readout temps at end
#define SMEM_TOTAL (O_NEW + 8192)       // 227840

// sub-offsets
#define O_ALS    O_HSS                  // float[410*3]
#define O_PERM   (O_HSS + 4920)         // int[410]
#define O_PART   O_NEW                  // float[16*60] (after s_new is dead)
#define O_GSUM   (O_NEW + 3840)         // float[60]
#define O_HB     (O_NEW + 4096)         // float[30]
#define O_ZB     (O_NEW + 4224)         // float[3]

__device__ __forceinline__ float lrelu(float x) { return x > 0.f ? x : 0.2f * x; }
__device__ __forceinline__ unsigned encf(float f) {
    unsigned u = __float_as_uint(f);
    return (u & 0x80000000u) ? ~u : (u | 0x80000000u);
}

// block-wide exclusive scan of per-thread sums (all T threads must call)
__device__ __forceinline__ int scan_ex(int s, int t, int* wsum) {
    __syncthreads();
    int lane = t & 31, wid = t >> 5;
    int x = s;
#pragma unroll
    for (int d = 1; d < 32; d <<= 1) {
        int y = __shfl_up_sync(0xFFFFFFFFu, x, d);
        if (lane >= d) x += y;
    }
    if (lane == 31) wsum[wid] = x;
    __syncthreads();
    if (t == 0) {
        int run = 0;
#pragma unroll
        for (int w = 0; w < NW; w++) { int tmp = wsum[w]; wsum[w] = run; run += tmp; }
    }
    __syncthreads();
    return wsum[wid] + x - s;
}

__global__ void __launch_bounds__(T, 1)
k_mega(const float* __restrict__ x,
       const int* __restrict__ src, const int* __restrict__ dst,
       const float* __restrict__ W1, const float* __restrict__ b1,
       const float* __restrict__ Ws, const float* __restrict__ bs,
       const float* __restrict__ Wg,
       const float* __restrict__ a_src, const float* __restrict__ a_dst,
       const float* __restrict__ bg,
       const float* __restrict__ Wf1, const float* __restrict__ bf1,
       const float* __restrict__ Wf2, const float* __restrict__ bf2,
       float* __restrict__ out)
{
    extern __shared__ char sm[];
    float*    s_hx   = (float*)(sm);                 // rows of 12
    float*    s_hG   = (float*)(sm);                 // rows of 64 (late)
    int*      s_csr  = (int*)(sm + O_CSR);
    int*      s_cnt  = (int*)(sm + O_CNT);
    int*      s_off  = (int*)(sm + O_OFF);
    int*      s_cur  = (int*)(sm + O_CUR);
    unsigned* s_enc  = (unsigned*)(sm + O_CUR);      // after P3
    float*    s_dinv = (float*)(sm + O_DINV);
    float*    s_hss  = (float*)(sm + O_HSS);
    int*      s_bins = (int*)(sm + O_HSS);           // radix bins (256)
    float*    s_als  = (float*)(sm + O_ALS);         // P8+
    int*      s_perm = (int*)(sm + O_PERM);          // P8+
    float*    s_scr  = (float*)(sm + O_SCORE);
    float*    s_ald  = (float*)(sm + O_SCORE);       // P8+
    int*      s_new  = (int*)(sm + O_NEW);
    float*    s_part = (float*)(sm + O_PART);
    float*    s_gsum = (float*)(sm + O_GSUM);
    float*    s_hb   = (float*)(sm + O_HB);
    float*    s_zb   = (float*)(sm + O_ZB);

    __shared__ float W1s[50], Wss[10], b1s[10], Wgs[600], asr[60], ads[60];
    __shared__ int wsum[NW];
    __shared__ unsigned sPrefix;
    __shared__ int sNeed, sDig, sRem;

    const int g = blockIdx.x;
    const int t = threadIdx.x;
    const int ebase = g * EPG;
    const int nbase = g * NN;
    const float bs0 = bs[0];

    // ---- P0: init + weight staging ----
    for (int i = t; i < NN; i += T) s_cnt[i] = 0;
    if (t < 50) W1s[t] = W1[t];
    if (t < 10) { Wss[t] = Ws[t]; b1s[t] = b1[t]; }
    if (t < 600) Wgs[t] = Wg[t];
    if (t < 60) { asr[t] = a_src[t]; ads[t] = a_dst[t]; }
    __syncthreads();

    // ---- P1: degree count ----
    for (int e = t; e < EPG; e += T)
        atomicAdd(&s_cnt[dst[ebase + e] & (NN - 1)], 1);

    // ---- P2: dinv + exclusive scan of cnt -> off, cur ----
    {
        __syncthreads();
        int v[2], i0 = t * 2;
#pragma unroll
        for (int q = 0; q < 2; q++) {
            v[q] = s_cnt[i0 + q];
            s_dinv[i0 + q] = rsqrtf((float)v[q] + 1.0f);
        }
        int ex = scan_ex(v[0] + v[1], t, wsum);
#pragma unroll
        for (int q = 0; q < 2; q++) { s_off[i0 + q] = ex; s_cur[i0 + q] = ex; ex += v[q]; }
    }
    __syncthreads();

    // ---- P3: packed CSR scatter ----
    for (int e = t; e < EPG; e += T) {
        int d = dst[ebase + e] & (NN - 1);
        int s = src[ebase + e] & (NN - 1);
        s_csr[atomicAdd(&s_cur[d], 1)] = s;
    }

    // ---- P4: hh1 = (x@W1)*dinv (12-wide rows, zero pad) ----
    __syncthreads();
    for (int i = t; i < NN; i += T) {
        float xi[5];
#pragma unroll
        for (int c = 0; c < 5; c++) xi[c] = x[(nbase + i) * 5 + c];
        float dv = s_dinv[i];
        float h[12];
#pragma unroll
        for (int k = 0; k < 10; k++) {
            float v = 0.f;
#pragma unroll
            for (int c = 0; c < 5; c++) v += xi[c] * W1s[c * 10 + k];
            h[k] = v * dv;
        }
        h[10] = 0.f; h[11] = 0.f;
        float4* o = (float4*)&s_hx[i * 12];
        o[0] = make_float4(h[0], h[1], h[2], h[3]);
        o[1] = make_float4(h[4], h[5], h[6], h[7]);
        o[2] = make_float4(h[8], h[9], h[10], h[11]);
    }
    __syncthreads();

    // ---- P5: GCN1 gather (float4) -> x1 in place + fused scorer hss ----
    {
        float4 a[2][3];
#pragma unroll
        for (int q = 0; q < 2; q++) {
            int i = t + q * T;
            const float4* me = (const float4*)&s_hx[i * 12];
            a[q][0] = me[0]; a[q][1] = me[1]; a[q][2] = me[2];
            int e0 = s_off[i], e1 = e0 + s_cnt[i];
            for (int e = e0; e < e1; e++) {
                const float4* r = (const float4*)&s_hx[s_csr[e] * 12];
                float4 r0 = r[0], r1 = r[1], r2 = r[2];
                a[q][0].x += r0.x; a[q][0].y += r0.y; a[q][0].z += r0.z; a[q][0].w += r0.w;
                a[q][1].x += r1.x; a[q][1].y += r1.y; a[q][1].z += r1.z; a[q][1].w += r1.w;
                a[q][2].x += r2.x; a[q][2].y += r2.y;
            }
        }
        __syncthreads();
#pragma unroll
        for (int q = 0; q < 2; q++) {
            int i = t + q * T;
            float dv = s_dinv[i];
            float v[10] = {a[q][0].x, a[q][0].y, a[q][0].z, a[q][0].w,
                           a[q][1].x, a[q][1].y, a[q][1].z, a[q][1].w,
                           a[q][2].x, a[q][2].y};
            float hs = 0.f;
#pragma unroll
            for (int k = 0; k < 10; k++) {
                v[k] = v[k] * dv + b1s[k];
                hs += v[k] * Wss[k];
            }
            float4* o = (float4*)&s_hx[i * 12];
            o[0] = make_float4(v[0], v[1], v[2], v[3]);
            o[1] = make_float4(v[4], v[5], v[6], v[7]);
            o[2] = make_float4(v[8], v[9], 0.f, 0.f);
            s_hss[i] = hs * dv;
        }
    }
    __syncthreads();

    // ---- P6: scorer gather -> score + enc ----
    for (int i = t; i < NN; i += T) {
        float sc = s_hss[i];
        int e0 = s_off[i], e1 = e0 + s_cnt[i];
        for (int e = e0; e < e1; e++) sc += s_hss[s_csr[e]];
        sc = sc * s_dinv[i] + bs0;
        s_scr[i] = sc;
        s_enc[i] = encf(sc);
    }
    __syncthreads();

    // ---- P7: top-K via 8-bit radix select on enc (descending), then compact --
    {
        if (t == 0) { sPrefix = 0u; sNeed = KK; }
        __syncthreads();
        int i0 = t * 2;
#pragma unroll
        for (int shift = 24; shift >= 0; shift -= 8) {
            if (t < 256) s_bins[t] = 0;
            __syncthreads();
            unsigned pfx = sPrefix;
#pragma unroll
            for (int q = 0; q < 2; q++) {
                unsigned e = s_enc[i0 + q];
                bool match = (shift == 24) || ((e >> (shift + 8)) == pfx);
                if (match) atomicAdd(&s_bins[(e >> shift) & 255], 1);
            }
            __syncthreads();
            int mycount = (t < 256) ? s_bins[255 - t] : 0;
            int ex = scan_ex(mycount, t, wsum);
            if (t < 256) {
                int need = sNeed;
                if (ex < need && need <= ex + mycount) {
                    sDig = 255 - t;
                    sRem = need - ex;
                }
            }
            __syncthreads();
            if (t == 0) { sPrefix = (sPrefix << 8) | (unsigned)sDig; sNeed = sRem; }
            __syncthreads();
        }
        unsigned KT = sPrefix;   // KK-th largest enc (tie value)
        int tneed = sNeed;       // ties to accept (smallest index first)
        int ng = KK - tneed;
        int pg[2], pt[2];
#pragma unroll
        for (int q = 0; q < 2; q++) {
            unsigned e = s_enc[i0 + q];
            pg[q] = (e > KT) ? 1 : 0;
            pt[q] = (e == KT) ? 1 : 0;
        }
        int exg = scan_ex(pg[0] + pg[1], t, wsum);
        int ext = scan_ex(pt[0] + pt[1], t, wsum);
#pragma unroll
        for (int q = 0; q < 2; q++) {
            int i = i0 + q;
            int slot = -1;
            if (pg[q]) slot = exg;
            else if (pt[q] && ext < tneed) slot = ng + ext;
            if (slot >= 0) { s_perm[slot] = i; s_new[i] = slot; }
            else s_new[i] = -1;
            exg += pg[q];
            ext += pt[q];
        }
    }
    __syncthreads();

    // ---- P8: pooled precompute over (node, head) units: 1230 units ----
    // hg row chunk of 20 per unit; als/ald per unit.
    {
        float hg[2][CC], as2[2], ad2[2];
#pragma unroll
        for (int pass = 0; pass < 2; pass++) {
            int u = t + pass * T;
            if (u >= KK * HH) break;
            int j = u / 3, h = u - 3 * j;
            int node = s_perm[j];
            float gate = tanhf(s_scr[node]);
            float xp[10];
#pragma unroll
            for (int c = 0; c < 10; c++) xp[c] = s_hx[node * 12 + c] * gate;
            float as = 0.f, ad = 0.f;
#pragma unroll
            for (int c = 0; c < CC; c++) {
                int k = h * CC + c;
                float v = 0.f;
#pragma unroll
                for (int q = 0; q < 10; q++) v += xp[q] * Wgs[q * 60 + k];
                hg[pass][c] = v;
                as += v * asr[k];
                ad += v * ads[k];
            }
            as2[pass] = as; ad2[pass] = ad;
        }
        __syncthreads();   // all reads of s_hx/s_scr done
#pragma unroll
        for (int pass = 0; pass < 2; pass++) {
            int u = t + pass * T;
            if (u >= KK * HH) break;
            int j = u / 3, h = u - 3 * j;
#pragma unroll
            for (int c = 0; c < CC; c++) s_hG[j * 64 + h * CC + c] = hg[pass][c];
            s_als[u] = as2[pass];
            s_ald[u] = ad2[pass];
        }
    }
    __syncthreads();

    // ---- P9: GAT softmax-aggregate over (node, head) units ----
    // logits ~1e-2: exp without max-subtraction is exact softmax.
    {
        float acc[2][CC];
#pragma unroll
        for (int pass = 0; pass < 2; pass++) {
            int u = t + pass * T;
            if (u >= KK * HH) break;
            int j = u / 3, h = u - 3 * j;
            int node = s_perm[j];
            float aldj = s_ald[u];
            float w = __expf(lrelu(s_als[u] + aldj));
            float den = w;
#pragma unroll
            for (int c = 0; c < CC; c++) acc[pass][c] = s_hG[j * 64 + h * CC + c] * w;
            int e0 = s_off[node], e1 = e0 + s_cnt[node];
            for (int e = e0; e < e1; e++) {
                int sj = s_new[s_csr[e]];
                if (sj < 0) continue;
                float ww = __expf(lrelu(s_als[sj * 3 + h] + aldj));
                den += ww;
                const float* row = &s_hG[sj * 64 + h * CC];
#pragma unroll
                for (int c = 0; c < CC; c++) acc[pass][c] += row[c] * ww;
            }
            float inv = 1.f / den;
#pragma unroll
            for (int c = 0; c < CC; c++) acc[pass][c] *= inv;
        }
        __syncthreads();   // all reads of s_hG done
#pragma unroll
        for (int pass = 0; pass < 2; pass++) {
            int u = t + pass * T;
            if (u >= KK * HH) break;
            int j = u / 3, h = u - 3 * j;
#pragma unroll
            for (int c = 0; c < CC; c++) s_hG[j * 64 + h * CC + c] = acc[pass][c];
        }
    }
    __syncthreads();

    // ---- readout reduction over 410 rows (16 groups of 64) ----
    {
        int col = t & 63, grp = t >> 6;
        if (col < 60) {
            float a = 0.f;
            for (int r = grp; r < KK; r += 16) a += s_hG[r * 64 + col];
            s_part[grp * 60 + col] = a;
        }
    }
    __syncthreads();
    if (t < 60) {
        float a = 0.f;
#pragma unroll
        for (int q = 0; q < 16; q++) a += s_part[q * 60 + t];
        s_gsum[t] = a + (float)KK * bg[t];
    }
    __syncthreads();

    // ---- MLP + log_softmax ----
    if (t < 30) {
        float v = bf1[t];
#pragma unroll
        for (int c = 0; c < 60; c++) v += s_gsum[c] * Wf1[c * 30 + t];
        s_hb[t] = v > 0.f ? v : 0.f;
    }
    __syncthreads();
    if (t < 3) {
        float v = bf2[t];
#pragma unroll
        for (int c = 0; c < 30; c++) v += s_hb[c] * Wf2[c * 3 + t];
        s_zb[t] = v;
    }
    __syncthreads();
    if (t == 0) {
        float m = fmaxf(s_zb[0], fmaxf(s_zb[1], s_zb[2]));
        float lse = logf(expf(s_zb[0] - m) + expf(s_zb[1] - m) + expf(s_zb[2] - m)) + m;
        out[g * 3 + 0] = s_zb[0] - lse;
        out[g * 3 + 1] = s_zb[1] - lse;
        out[g * 3 + 2] = s_zb[2] - lse;
    }
}

// ---------------- launch -----------------------------------------------------
extern "C" void kernel_launch(void* const* d_in, const int* in_sizes, int n_in,
                              void* d_out, int out_size) {
    const float* x     = (const float*)d_in[0];
    const int*   src   = (const int*)d_in[1];
    const int*   dst   = (const int*)d_in[2];
    const float* W1    = (const float*)d_in[4];
    const float* b1    = (const float*)d_in[5];
    const float* Ws    = (const float*)d_in[6];
    const float* bs    = (const float*)d_in[7];
    const float* Wg    = (const float*)d_in[8];
    const float* a_src = (const float*)d_in[9];
    const float* a_dst = (const float*)d_in[10];
    const float* bg    = (const float*)d_in[11];
    const float* Wf1   = (const float*)d_in[12];
    const float* bf1   = (const float*)d_in[13];
    const float* Wf2   = (const float*)d_in[14];
    const float* bf2   = (const float*)d_in[15];
    float* out = (float*)d_out;

    static int attr_set = 0;
    if (!attr_set) {
        cudaFuncSetAttribute(k_mega, cudaFuncAttributeMaxDynamicSharedMemorySize,
                             SMEM_TOTAL);
        attr_set = 1;
    }
    k_mega<<<NGR, T, SMEM_TOTAL>>>(x, src, dst, W1, b1, Ws, bs, Wg, a_src, a_dst,
                                   bg, Wf1, bf1, Wf2, bf2, out);
}

// round 11
// speedup vs baseline: 1.1711x; 1.0791x over previous
#include <cuda_runtime.h>

#define NGR  64
#define NN   2048
#define EPG  16384          // edges per graph
#define KK   410
#define HH   3
#define CC   20
#define T    1024
#define NW   (T / 32)
#define EPT  (EPG / T)      // 16 edges per thread

// ---------------- dynamic smem layout (bytes) -------------------------------
// Region A: hh1/x1 rows of 12 floats (98304 B) -> later hG rows of 64 (104960 B)
#define SZ_A     104960
#define O_CSR    SZ_A                   // int[16384]
#define O_CNT    (O_CSR + 65536)        // int[2048]
#define O_OFF    (O_CNT + 8192)         // int[2048]
#define O_CUR    (O_OFF + 8192)         // cursors (P3); enc u32[2048] (P6+)
#define O_DINV   (O_CUR + 8192)         // float[2048] dinv; gate[410] (P8+)
#define O_HSS    (O_DINV + 8192)        // hss; radix bins[2048]; als+perm (P8+)
#define O_SCORE  (O_HSS + 8192)         // score; ald (P8+)
#define O_NEW    (O_SCORE + 8192)       // newidx; readout temps at end
#define SMEM_TOTAL (O_NEW + 8192)       // 227840

// sub-offsets
#define O_ALS    O_HSS                  // float[410*3]
#define O_PERM   (O_HSS + 4920)         // int[410]
#define O_PART   O_NEW                  // float[16*60] (after s_new is dead)
#define O_GSUM   (O_NEW + 3840)         // float[60]
#define O_HB     (O_NEW + 4096)         // float[30]
#define O_ZB     (O_NEW + 4224)         // float[3]

__device__ __forceinline__ float lrelu(float x) { return x > 0.f ? x : 0.2f * x; }
__device__ __forceinline__ unsigned encf(float f) {
    unsigned u = __float_as_uint(f);
    return (u & 0x80000000u) ? ~u : (u | 0x80000000u);
}

// block-wide exclusive scan of per-thread sums (all T threads must call)
__device__ __forceinline__ int scan_ex(int s, int t, int* wsum) {
    __syncthreads();
    int lane = t & 31, wid = t >> 5;
    int x = s;
#pragma unroll
    for (int d = 1; d < 32; d <<= 1) {
        int y = __shfl_up_sync(0xFFFFFFFFu, x, d);
        if (lane >= d) x += y;
    }
    if (lane == 31) wsum[wid] = x;
    __syncthreads();
    if (t == 0) {
        int run = 0;
#pragma unroll
        for (int w = 0; w < NW; w++) { int tmp = wsum[w]; wsum[w] = run; run += tmp; }
    }
    __syncthreads();
    return wsum[wid] + x - s;
}

__global__ void __launch_bounds__(T, 1)
k_mega(const float* __restrict__ x,
       const int* __restrict__ src, const int* __restrict__ dst,
       const float* __restrict__ W1, const float* __restrict__ b1,
       const float* __restrict__ Ws, const float* __restrict__ bs,
       const float* __restrict__ Wg,
       const float* __restrict__ a_src, const float* __restrict__ a_dst,
       const float* __restrict__ bg,
       const float* __restrict__ Wf1, const float* __restrict__ bf1,
       const float* __restrict__ Wf2, const float* __restrict__ bf2,
       float* __restrict__ out)
{
    extern __shared__ char sm[];
    float*    s_hx   = (float*)(sm);                 // rows of 12
    float*    s_hG   = (float*)(sm);                 // rows of 64 (late)
    int*      s_csr  = (int*)(sm + O_CSR);
    int*      s_cnt  = (int*)(sm + O_CNT);
    int*      s_off  = (int*)(sm + O_OFF);
    int*      s_cur  = (int*)(sm + O_CUR);
    unsigned* s_enc  = (unsigned*)(sm + O_CUR);      // after P3
    float*    s_dinv = (float*)(sm + O_DINV);
    float*    s_gate = (float*)(sm + O_DINV);        // after P7 (dinv dead)
    float*    s_hss  = (float*)(sm + O_HSS);
    int*      s_bins = (int*)(sm + O_HSS);           // radix bins (2048)
    float*    s_als  = (float*)(sm + O_ALS);         // P8+
    int*      s_perm = (int*)(sm + O_PERM);          // P8+
    float*    s_scr  = (float*)(sm + O_SCORE);
    float*    s_ald  = (float*)(sm + O_SCORE);       // P8+
    int*      s_new  = (int*)(sm + O_NEW);
    float*    s_part = (float*)(sm + O_PART);
    float*    s_gsum = (float*)(sm + O_GSUM);
    float*    s_hb   = (float*)(sm + O_HB);
    float*    s_zb   = (float*)(sm + O_ZB);

    __shared__ float W1s[50], Wss[10], b1s[10], Wgs[600], asr[60], ads[60];
    __shared__ int wsum[NW];
    __shared__ unsigned sPrefix;
    __shared__ int sNeed, sDig, sRem;

    const int g = blockIdx.x;
    const int t = threadIdx.x;
    const int ebase = g * EPG;
    const int nbase = g * NN;
    const float bs0 = bs[0];

    // ---- P0: register-cache edge list (ONE global read) + init + weights ----
    unsigned er[EPT];
    {
        const int4* s4 = (const int4*)(src + ebase);
        const int4* d4 = (const int4*)(dst + ebase);
#pragma unroll
        for (int r = 0; r < EPT / 4; r++) {
            int4 dv = d4[t + r * T];
            int4 sv = s4[t + r * T];
            er[r * 4 + 0] = ((unsigned)(dv.x & (NN - 1)) << 11) | (unsigned)(sv.x & (NN - 1));
            er[r * 4 + 1] = ((unsigned)(dv.y & (NN - 1)) << 11) | (unsigned)(sv.y & (NN - 1));
            er[r * 4 + 2] = ((unsigned)(dv.z & (NN - 1)) << 11) | (unsigned)(sv.z & (NN - 1));
            er[r * 4 + 3] = ((unsigned)(dv.w & (NN - 1)) << 11) | (unsigned)(sv.w & (NN - 1));
        }
    }
    for (int i = t; i < NN; i += T) s_cnt[i] = 0;
    if (t < 50) W1s[t] = W1[t];
    if (t < 10) { Wss[t] = Ws[t]; b1s[t] = b1[t]; }
    if (t < 600) Wgs[t] = Wg[t];
    if (t < 60) { asr[t] = a_src[t]; ads[t] = a_dst[t]; }
    __syncthreads();

    // ---- P1: degree count from regs ----
#pragma unroll
    for (int r = 0; r < EPT; r++)
        atomicAdd(&s_cnt[er[r] >> 11], 1);

    // ---- P2 (fused): scan -> off/cur ; dinv ; hh1 = (x@W1)*dinv ----
    {
        __syncthreads();
        int v[2], i0 = t * 2;
        v[0] = s_cnt[i0];
        v[1] = s_cnt[i0 + 1];
        int ex = scan_ex(v[0] + v[1], t, wsum);
#pragma unroll
        for (int q = 0; q < 2; q++) {
            int i = i0 + q;
            s_off[i] = ex; s_cur[i] = ex; ex += v[q];
            float dv = rsqrtf((float)v[q] + 1.0f);
            s_dinv[i] = dv;
            float xi[5];
#pragma unroll
            for (int c = 0; c < 5; c++) xi[c] = x[(nbase + i) * 5 + c];
            float h[12];
#pragma unroll
            for (int k = 0; k < 10; k++) {
                float vv = 0.f;
#pragma unroll
                for (int c = 0; c < 5; c++) vv += xi[c] * W1s[c * 10 + k];
                h[k] = vv * dv;
            }
            h[10] = 0.f; h[11] = 0.f;
            float4* o = (float4*)&s_hx[i * 12];
            o[0] = make_float4(h[0], h[1], h[2], h[3]);
            o[1] = make_float4(h[4], h[5], h[6], h[7]);
            o[2] = make_float4(h[8], h[9], h[10], h[11]);
        }
    }
    __syncthreads();

    // ---- P3: packed CSR scatter from regs ----
#pragma unroll
    for (int r = 0; r < EPT; r++) {
        int d = (int)(er[r] >> 11);
        int s = (int)(er[r] & (NN - 1));
        s_csr[atomicAdd(&s_cur[d], 1)] = s;
    }
    __syncthreads();

    // ---- P5: GCN1 gather (float4) -> x1 in place + fused scorer hss ----
    {
        float4 a[2][3];
#pragma unroll
        for (int q = 0; q < 2; q++) {
            int i = t + q * T;
            const float4* me = (const float4*)&s_hx[i * 12];
            a[q][0] = me[0]; a[q][1] = me[1]; a[q][2] = me[2];
            int e0 = s_off[i], e1 = e0 + s_cnt[i];
            for (int e = e0; e < e1; e++) {
                const float4* r = (const float4*)&s_hx[s_csr[e] * 12];
                float4 r0 = r[0], r1 = r[1], r2 = r[2];
                a[q][0].x += r0.x; a[q][0].y += r0.y; a[q][0].z += r0.z; a[q][0].w += r0.w;
                a[q][1].x += r1.x; a[q][1].y += r1.y; a[q][1].z += r1.z; a[q][1].w += r1.w;
                a[q][2].x += r2.x; a[q][2].y += r2.y;
            }
        }
        __syncthreads();
#pragma unroll
        for (int q = 0; q < 2; q++) {
            int i = t + q * T;
            float dv = s_dinv[i];
            float v[10] = {a[q][0].x, a[q][0].y, a[q][0].z, a[q][0].w,
                           a[q][1].x, a[q][1].y, a[q][1].z, a[q][1].w,
                           a[q][2].x, a[q][2].y};
            float hs = 0.f;
#pragma unroll
            for (int k = 0; k < 10; k++) {
                v[k] = v[k] * dv + b1s[k];
                hs += v[k] * Wss[k];
            }
            float4* o = (float4*)&s_hx[i * 12];
            o[0] = make_float4(v[0], v[1], v[2], v[3]);
            o[1] = make_float4(v[4], v[5], v[6], v[7]);
            o[2] = make_float4(v[8], v[9], 0.f, 0.f);
            s_hss[i] = hs * dv;
        }
    }
    __syncthreads();

    // ---- P6: scorer gather -> score + enc ----
    unsigned e0v, e1v;
    for (int i = t; i < NN; i += T) {
        float sc = s_hss[i];
        int e0 = s_off[i], e1 = e0 + s_cnt[i];
        for (int e = e0; e < e1; e++) sc += s_hss[s_csr[e]];
        sc = sc * s_dinv[i] + bs0;
        s_scr[i] = sc;
        s_enc[i] = encf(sc);
    }
    __syncthreads();
    e0v = s_enc[2 * t];
    e1v = s_enc[2 * t + 1];

    // ---- P7: top-K via 3-pass radix select (11/11/10 bits, descending) ----
    {
        int i0 = 2 * t;
        if (t == 0) { sPrefix = 0u; sNeed = KK; }

        // pass 0: bits [21,32)
        s_bins[i0] = 0; s_bins[i0 + 1] = 0;
        __syncthreads();
        atomicAdd(&s_bins[e0v >> 21], 1);
        atomicAdd(&s_bins[e1v >> 21], 1);
        {
            int c0, c1;
            __syncthreads();
            c0 = s_bins[2047 - i0]; c1 = s_bins[2046 - i0];
            int ex = scan_ex(c0 + c1, t, wsum);
            int need = sNeed;
            if (ex < need && need <= ex + c0)            { sDig = 2047 - i0; sRem = need - ex; }
            else if (ex + c0 < need && need <= ex + c0 + c1) { sDig = 2046 - i0; sRem = need - ex - c0; }
            __syncthreads();
            if (t == 0) { sPrefix = (unsigned)sDig; sNeed = sRem; }
        }
        __syncthreads();

        // pass 1: bits [10,21)
        s_bins[i0] = 0; s_bins[i0 + 1] = 0;
        __syncthreads();
        {
            unsigned pfx = sPrefix;
            if ((e0v >> 21) == pfx) atomicAdd(&s_bins[(e0v >> 10) & 2047], 1);
            if ((e1v >> 21) == pfx) atomicAdd(&s_bins[(e1v >> 10) & 2047], 1);
            int c0, c1;
            __syncthreads();
            c0 = s_bins[2047 - i0]; c1 = s_bins[2046 - i0];
            int ex = scan_ex(c0 + c1, t, wsum);
            int need = sNeed;
            if (ex < need && need <= ex + c0)            { sDig = 2047 - i0; sRem = need - ex; }
            else if (ex + c0 < need && need <= ex + c0 + c1) { sDig = 2046 - i0; sRem = need - ex - c0; }
            __syncthreads();
            if (t == 0) { sPrefix = (sPrefix << 11) | (unsigned)sDig; sNeed = sRem; }
        }
        __syncthreads();

        // pass 2: bits [0,10) (1024 bins; T==1024 so one bin/thread)
        s_bins[t] = 0;
        __syncthreads();
        {
            unsigned pfx = sPrefix;
            if ((e0v >> 10) == pfx) atomicAdd(&s_bins[e0v & 1023], 1);
            if ((e1v >> 10) == pfx) atomicAdd(&s_bins[e1v & 1023], 1);
            int c;
            __syncthreads();
            c = s_bins[1023 - t];
            int ex = scan_ex(c, t, wsum);
            int need = sNeed;
            if (ex < need && need <= ex + c) { sDig = 1023 - t; sRem = need - ex; }
            __syncthreads();
            if (t == 0) { sPrefix = (sPrefix << 10) | (unsigned)sDig; sNeed = sRem; }
        }
        __syncthreads();

        unsigned KT = sPrefix;   // KK-th largest enc (tie value)
        int tneed = sNeed;       // ties to accept (smallest index first)
        int ng = KK - tneed;
        int pg[2], pt[2];
        pg[0] = (e0v > KT) ? 1 : 0;  pt[0] = (e0v == KT) ? 1 : 0;
        pg[1] = (e1v > KT) ? 1 : 0;  pt[1] = (e1v == KT) ? 1 : 0;
        int exg = scan_ex(pg[0] + pg[1], t, wsum);
        int ext = scan_ex(pt[0] + pt[1], t, wsum);
#pragma unroll
        for (int q = 0; q < 2; q++) {
            int i = i0 + q;
            int slot = -1;
            if (pg[q]) slot = exg;
            else if (pt[q] && ext < tneed) slot = ng + ext;
            if (slot >= 0) { s_perm[slot] = i; s_new[i] = slot; }
            else s_new[i] = -1;
            exg += pg[q];
            ext += pt[q];
        }
    }
    __syncthreads();

    // ---- gates: 410 tanhf once (dinv region is dead -> s_gate) ----
    if (t < KK) s_gate[t] = tanhf(s_scr[s_perm[t]]);
    __syncthreads();

    // ---- P8: pooled precompute over (node, head) units: 1230 units ----
    {
        float hg[2][CC], as2[2], ad2[2];
#pragma unroll
        for (int pass = 0; pass < 2; pass++) {
            int u = t + pass * T;
            if (u >= KK * HH) break;
            int j = u / 3, h = u - 3 * j;
            int node = s_perm[j];
            float gate = s_gate[j];
            float xp[10];
#pragma unroll
            for (int c = 0; c < 10; c++) xp[c] = s_hx[node * 12 + c] * gate;
            float as = 0.f, ad = 0.f;
#pragma unroll
            for (int c = 0; c < CC; c++) {
                int k = h * CC + c;
                float v = 0.f;
#pragma unroll
                for (int q = 0; q < 10; q++) v += xp[q] * Wgs[q * 60 + k];
                hg[pass][c] = v;
                as += v * asr[k];
                ad += v * ads[k];
            }
            as2[pass] = as; ad2[pass] = ad;
        }
        __syncthreads();   // all reads of s_hx/s_scr done
#pragma unroll
        for (int pass = 0; pass < 2; pass++) {
            int u = t + pass * T;
            if (u >= KK * HH) break;
            int j = u / 3, h = u - 3 * j;
#pragma unroll
            for (int c = 0; c < CC; c++) s_hG[j * 64 + h * CC + c] = hg[pass][c];
            s_als[u] = as2[pass];
            s_ald[u] = ad2[pass];
        }
    }
    __syncthreads();

    // ---- P9: GAT softmax-aggregate over (node, head) units ----
    // logits ~1e-2: exp without max-subtraction is exact softmax.
    {
        float acc[2][CC];
#pragma unroll
        for (int pass = 0; pass < 2; pass++) {
            int u = t + pass * T;
            if (u >= KK * HH) break;
            int j = u / 3, h = u - 3 * j;
            int node = s_perm[j];
            float aldj = s_ald[u];
            float w = __expf(lrelu(s_als[u] + aldj));
            float den = w;
#pragma unroll
            for (int c = 0; c < CC; c++) acc[pass][c] = s_hG[j * 64 + h * CC + c] * w;
            int e0 = s_off[node], e1 = e0 + s_cnt[node];
            for (int e = e0; e < e1; e++) {
                int sj = s_new[s_csr[e]];
                if (sj < 0) continue;
                float ww = __expf(lrelu(s_als[sj * 3 + h] + aldj));
                den += ww;
                const float* row = &s_hG[sj * 64 + h * CC];
#pragma unroll
                for (int c = 0; c < CC; c++) acc[pass][c] += row[c] * ww;
            }
            float inv = 1.f / den;
#pragma unroll
            for (int c = 0; c < CC; c++) acc[pass][c] *= inv;
        }
        __syncthreads();   // all reads of s_hG done
#pragma unroll
        for (int pass = 0; pass < 2; pass++) {
            int u = t + pass * T;
            if (u >= KK * HH) break;
            int j = u / 3, h = u - 3 * j;
#pragma unroll
            for (int c = 0; c < CC; c++) s_hG[j * 64 + h * CC + c] = acc[pass][c];
        }
    }
    __syncthreads();

    // ---- readout reduction over 410 rows (16 groups of 64) ----
    {
        int col = t & 63, grp = t >> 6;
        if (col < 60) {
            float a = 0.f;
            for (int r = grp; r < KK; r += 16) a += s_hG[r * 64 + col];
            s_part[grp * 60 + col] = a;
        }
    }
    __syncthreads();
    if (t < 60) {
        float a = 0.f;
#pragma unroll
        for (int q = 0; q < 16; q++) a += s_part[q * 60 + t];
        s_gsum[t] = a + (float)KK * bg[t];
    }
    __syncthreads();

    // ---- MLP + log_softmax ----
    if (t < 30) {
        float v = bf1[t];
#pragma unroll
        for (int c = 0; c < 60; c++) v += s_gsum[c] * Wf1[c * 30 + t];
        s_hb[t] = v > 0.f ? v : 0.f;
    }
    __syncthreads();
    if (t < 3) {
        float v = bf2[t];
#pragma unroll
        for (int c = 0; c < 30; c++) v += s_hb[c] * Wf2[c * 3 + t];
        s_zb[t] = v;
    }
    __syncthreads();
    if (t == 0) {
        float m = fmaxf(s_zb[0], fmaxf(s_zb[1], s_zb[2]));
        float lse = logf(expf(s_zb[0] - m) + expf(s_zb[1] - m) + expf(s_zb[2] - m)) + m;
        out[g * 3 + 0] = s_zb[0] - lse;
        out[g * 3 + 1] = s_zb[1] - lse;
        out[g * 3 + 2] = s_zb[2] - lse;
    }
}

// ---------------- launch -----------------------------------------------------
extern "C" void kernel_launch(void* const* d_in, const int* in_sizes, int n_in,
                              void* d_out, int out_size) {
    const float* x     = (const float*)d_in[0];
    const int*   src   = (const int*)d_in[1];
    const int*   dst   = (const int*)d_in[2];
    const float* W1    = (const float*)d_in[4];
    const float* b1    = (const float*)d_in[5];
    const float* Ws    = (const float*)d_in[6];
    const float* bs    = (const float*)d_in[7];
    const float* Wg    = (const float*)d_in[8];
    const float* a_src = (const float*)d_in[9];
    const float* a_dst = (const float*)d_in[10];
    const float* bg    = (const float*)d_in[11];
    const float* Wf1   = (const float*)d_in[12];
    const float* bf1   = (const float*)d_in[13];
    const float* Wf2   = (const float*)d_in[14];
    const float* bf2   = (const float*)d_in[15];
    float* out = (float*)d_out;

    static int attr_set = 0;
    if (!attr_set) {
        cudaFuncSetAttribute(k_mega, cudaFuncAttributeMaxDynamicSharedMemorySize,
                             SMEM_TOTAL);
        attr_set = 1;
    }
    k_mega<<<NGR, T, SMEM_TOTAL>>>(x, src, dst, W1, b1, Ws, bs, Wg, a_src, a_dst,
                                   bg, Wf1, bf1, Wf2, bf2, out);
}

// round 13
// speedup vs baseline: 1.3219x; 1.1287x over previous
#include <cuda_runtime.h>
#include <cstdint>

#define NGR  64
#define NN   2048
#define NH   1024            // nodes per half (per CTA)
#define EPG  16384           // edges per graph
#define KK   410
#define HH   3
#define CC   20
#define T    1024
#define NW   (T / 32)
#define EPT  (EPG / T)       // 16 edges cached per thread

// ---------------- dynamic smem layout (bytes, per CTA) ----------------------
// Region A: hh1/x1 rows of 12 floats (full 2048 nodes, 98304 B)
//           -> later hG rows of 64 floats indexed by global pooled j (104960 B)
#define SZ_A     104960
#define O_CSR    SZ_A                   // int[10240] own-half CSR (exp ~8192)
#define O_CNT    (O_CSR + 40960)        // int[1024] own-half degree
#define O_OFF    (O_CNT + 4096)         // int[1024]
#define O_CUR    (O_OFF + 4096)         // int[1024]
#define O_DINV   (O_CUR + 4096)         // float[2048] full; gate[410] later
#define O_HSS    (O_DINV + 8192)        // float[2048] full; bins; als+perm later
#define O_SCR    (O_HSS + 8192)         // float[2048] own half valid; ald later
#define O_ENC    (O_SCR + 8192)         // u32[2048] full
#define O_NEW    (O_ENC + 8192)         // int[2048]; readout temps later
#define SMEM_TOTAL (O_NEW + 8192)       // 199168

#define O_ALS    O_HSS                  // float[1230]
#define O_PERM   (O_HSS + 4920)         // int[410]
#define O_ALD    O_SCR                  // float[1230]
#define O_GATE   O_DINV                 // float[410]
#define O_PART   O_NEW                  // float[16*60]
#define O_GSUM   (O_NEW + 3840)         // float[60]
#define O_HB     (O_NEW + 4352)         // float[30]
#define O_ZB     (O_NEW + 4480)         // float[3]

__device__ __forceinline__ float lrelu(float x) { return x > 0.f ? x : 0.2f * x; }
__device__ __forceinline__ unsigned encf(float f) {
    unsigned u = __float_as_uint(f);
    return (u & 0x80000000u) ? ~u : (u | 0x80000000u);
}
__device__ __forceinline__ uint32_t s2u(const void* p) {
    return (uint32_t)__cvta_generic_to_shared(p);
}
__device__ __forceinline__ uint32_t mapa_u32(uint32_t a, uint32_t r) {
    uint32_t d; asm("mapa.shared::cluster.u32 %0, %1, %2;" : "=r"(d) : "r"(a), "r"(r));
    return d;
}
__device__ __forceinline__ float ldc_f32(uint32_t a) {
    float v; asm volatile("ld.shared::cluster.f32 %0, [%1];" : "=f"(v) : "r"(a)); return v;
}
__device__ __forceinline__ unsigned ldc_u32(uint32_t a) {
    unsigned v; asm volatile("ld.shared::cluster.u32 %0, [%1];" : "=r"(v) : "r"(a)); return v;
}
__device__ __forceinline__ float4 ldc_f4(uint32_t a) {
    float4 v;
    asm volatile("ld.shared::cluster.v4.f32 {%0,%1,%2,%3}, [%4];"
                 : "=f"(v.x), "=f"(v.y), "=f"(v.z), "=f"(v.w) : "r"(a));
    return v;
}
#define CLUSTER_SYNC() do { \
    asm volatile("barrier.cluster.arrive.aligned;" ::: "memory"); \
    asm volatile("barrier.cluster.wait.aligned;" ::: "memory"); } while (0)

// block-wide exclusive scan of per-thread sums (all T threads must call)
__device__ __forceinline__ int scan_ex(int s, int t, int* wsum) {
    __syncthreads();
    int lane = t & 31, wid = t >> 5;
    int x = s;
#pragma unroll
    for (int d = 1; d < 32; d <<= 1) {
        int y = __shfl_up_sync(0xFFFFFFFFu, x, d);
        if (lane >= d) x += y;
    }
    if (lane == 31) wsum[wid] = x;
    __syncthreads();
    if (t == 0) {
        int run = 0;
#pragma unroll
        for (int w = 0; w < NW; w++) { int tmp = wsum[w]; wsum[w] = run; run += tmp; }
    }
    __syncthreads();
    return wsum[wid] + x - s;
}

__global__ void __launch_bounds__(T, 1) __cluster_dims__(2, 1, 1)
k_mega(const float* __restrict__ x,
       const int* __restrict__ src, const int* __restrict__ dst,
       const float* __restrict__ W1, const float* __restrict__ b1,
       const float* __restrict__ Ws, const float* __restrict__ bs,
       const float* __restrict__ Wg,
       const float* __restrict__ a_src, const float* __restrict__ a_dst,
       const float* __restrict__ bg,
       const float* __restrict__ Wf1, const float* __restrict__ bf1,
       const float* __restrict__ Wf2, const float* __restrict__ bf2,
       float* __restrict__ out)
{
    extern __shared__ char sm[];
    float*    s_hx   = (float*)(sm);                 // rows of 12 (full graph)
    float*    s_hG   = (float*)(sm);                 // rows of 64 by global j
    int*      s_csr  = (int*)(sm + O_CSR);
    int*      s_cnt  = (int*)(sm + O_CNT);
    int*      s_off  = (int*)(sm + O_OFF);
    int*      s_cur  = (int*)(sm + O_CUR);
    float*    s_dinv = (float*)(sm + O_DINV);
    float*    s_gate = (float*)(sm + O_GATE);
    float*    s_hss  = (float*)(sm + O_HSS);
    int*      s_bins = (int*)(sm + O_HSS);
    float*    s_als  = (float*)(sm + O_ALS);
    int*      s_perm = (int*)(sm + O_PERM);
    float*    s_scr  = (float*)(sm + O_SCR);
    float*    s_ald  = (float*)(sm + O_ALD);
    unsigned* s_enc  = (unsigned*)(sm + O_ENC);
    int*      s_new  = (int*)(sm + O_NEW);
    float*    s_part = (float*)(sm + O_PART);
    float*    s_gsum = (float*)(sm + O_GSUM);
    float*    s_hb   = (float*)(sm + O_HB);
    float*    s_zb   = (float*)(sm + O_ZB);

    __shared__ float W1s[50], Wss[10], b1s[10], Wgs[600], asr[60], ads[60];
    __shared__ int wsum[NW];
    __shared__ unsigned sPrefix;
    __shared__ int sNeed, sDig, sRem;

    const int g    = blockIdx.x >> 1;
    const unsigned rank = blockIdx.x & 1;      // == cluster_ctarank for (2,1,1)
    const unsigned peer = rank ^ 1;
    const int t = threadIdx.x;
    const int ebase = g * EPG;
    const int nbase = g * NN;
    const int hbase = (int)rank * NH;          // own node range start
    const float bs0 = bs[0];

    // ---- P0: register-cache full edge list + init + weights ----
    unsigned er[EPT];
    {
        const int4* s4 = (const int4*)(src + ebase);
        const int4* d4 = (const int4*)(dst + ebase);
#pragma unroll
        for (int r = 0; r < EPT / 4; r++) {
            int4 dv = d4[t + r * T];
            int4 sv = s4[t + r * T];
            er[r * 4 + 0] = ((unsigned)(dv.x & (NN - 1)) << 11) | (unsigned)(sv.x & (NN - 1));
            er[r * 4 + 1] = ((unsigned)(dv.y & (NN - 1)) << 11) | (unsigned)(sv.y & (NN - 1));
            er[r * 4 + 2] = ((unsigned)(dv.z & (NN - 1)) << 11) | (unsigned)(sv.z & (NN - 1));
            er[r * 4 + 3] = ((unsigned)(dv.w & (NN - 1)) << 11) | (unsigned)(sv.w & (NN - 1));
        }
    }
    s_cnt[t] = 0;
    if (t < 50) W1s[t] = W1[t];
    if (t < 10) { Wss[t] = Ws[t]; b1s[t] = b1[t]; }
    if (t < 600) Wgs[t] = Wg[t];
    if (t < 60) { asr[t] = a_src[t]; ads[t] = a_dst[t]; }
    __syncthreads();

    // ---- P1: degree count (own-half dsts only) ----
#pragma unroll
    for (int r = 0; r < EPT; r++)
        if ((er[r] >> 21) == rank) atomicAdd(&s_cnt[(er[r] >> 11) & (NH - 1)], 1);

    // ---- P2a: scan (1 cnt/thread) + own dinv ----
    {
        __syncthreads();
        int v = s_cnt[t];
        int ex = scan_ex(v, t, wsum);
        s_off[t] = ex; s_cur[t] = ex;
        s_dinv[hbase + t] = rsqrtf((float)v + 1.0f);
    }
    __syncthreads();

    // ---- P3: own-half CSR scatter ----
#pragma unroll
    for (int r = 0; r < EPT; r++) {
        if ((er[r] >> 21) == rank) {
            int dl = (int)((er[r] >> 11) & (NH - 1));
            s_csr[atomicAdd(&s_cur[dl], 1)] = (int)(er[r] & (NN - 1));
        }
    }
    CLUSTER_SYNC();     // own dinv half + CSR done in both CTAs

    // ---- P2b: copy peer dinv half; P4: hh1 for ALL nodes (replicated) ----
    {
        int i = (int)peer * NH + t;
        s_dinv[i] = ldc_f32(mapa_u32(s2u(&s_dinv[i]), peer));
    }
    __syncthreads();
#pragma unroll
    for (int q = 0; q < 2; q++) {
        int i = t + q * T;
        float dv = s_dinv[i];
        float xi[5];
#pragma unroll
        for (int c = 0; c < 5; c++) xi[c] = x[(nbase + i) * 5 + c];
        float h[12];
#pragma unroll
        for (int k = 0; k < 10; k++) {
            float vv = 0.f;
#pragma unroll
            for (int c = 0; c < 5; c++) vv += xi[c] * W1s[c * 10 + k];
            h[k] = vv * dv;
        }
        h[10] = 0.f; h[11] = 0.f;
        float4* o = (float4*)&s_hx[i * 12];
        o[0] = make_float4(h[0], h[1], h[2], h[3]);
        o[1] = make_float4(h[4], h[5], h[6], h[7]);
        o[2] = make_float4(h[8], h[9], h[10], h[11]);
    }
    __syncthreads();

    // ---- P5: GCN1 gather for own 1024 dsts (1 node/thread) + scorer hss ----
    {
        int i = hbase + t;
        const float4* me = (const float4*)&s_hx[i * 12];
        float4 a0 = me[0], a1 = me[1], a2 = me[2];
        int e0 = s_off[t], e1 = e0 + s_cnt[t];
        for (int e = e0; e < e1; e++) {
            const float4* r = (const float4*)&s_hx[s_csr[e] * 12];
            float4 r0 = r[0], r1 = r[1], r2 = r[2];
            a0.x += r0.x; a0.y += r0.y; a0.z += r0.z; a0.w += r0.w;
            a1.x += r1.x; a1.y += r1.y; a1.z += r1.z; a1.w += r1.w;
            a2.x += r2.x; a2.y += r2.y;
        }
        __syncthreads();     // all local hh1 reads done before x1 overwrite
        float dv = s_dinv[i];
        float v[10] = {a0.x, a0.y, a0.z, a0.w, a1.x, a1.y, a1.z, a1.w, a2.x, a2.y};
        float hs = 0.f;
#pragma unroll
        for (int k = 0; k < 10; k++) {
            v[k] = v[k] * dv + b1s[k];
            hs += v[k] * Wss[k];
        }
        float4* o = (float4*)&s_hx[i * 12];
        o[0] = make_float4(v[0], v[1], v[2], v[3]);
        o[1] = make_float4(v[4], v[5], v[6], v[7]);
        o[2] = make_float4(v[8], v[9], 0.f, 0.f);
        s_hss[i] = hs * dv;
    }
    CLUSTER_SYNC();     // peer hss half ready

    // ---- P5b: copy peer hss half ----
    {
        int i = (int)peer * NH + t;
        s_hss[i] = ldc_f32(mapa_u32(s2u(&s_hss[i]), peer));
    }
    __syncthreads();

    // ---- P6: scorer gather for own dsts -> score + enc ----
    {
        int i = hbase + t;
        float sc = s_hss[i];
        int e0 = s_off[t], e1 = e0 + s_cnt[t];
        for (int e = e0; e < e1; e++) sc += s_hss[s_csr[e]];
        sc = sc * s_dinv[i] + bs0;
        s_scr[i] = sc;
        s_enc[i] = encf(sc);
    }
    CLUSTER_SYNC();     // peer enc half ready

    // ---- P6b: copy peer enc half ----
    {
        int i = (int)peer * NH + t;
        s_enc[i] = ldc_u32(mapa_u32(s2u(&s_enc[i]), peer));
    }
    __syncthreads();
    unsigned e0v = s_enc[2 * t];
    unsigned e1v = s_enc[2 * t + 1];

    // ---- P7: top-K radix select (3 passes 11/11/10 bits) — run in BOTH CTAs
    //      on identical enc -> identical perm/new. ----
    {
        int i0 = 2 * t;
        if (t == 0) { sPrefix = 0u; sNeed = KK; }

        s_bins[i0] = 0; s_bins[i0 + 1] = 0;
        __syncthreads();
        atomicAdd(&s_bins[e0v >> 21], 1);
        atomicAdd(&s_bins[e1v >> 21], 1);
        {
            int c0, c1;
            __syncthreads();
            c0 = s_bins[2047 - i0]; c1 = s_bins[2046 - i0];
            int ex = scan_ex(c0 + c1, t, wsum);
            int need = sNeed;
            if (ex < need && need <= ex + c0)                 { sDig = 2047 - i0; sRem = need - ex; }
            else if (ex + c0 < need && need <= ex + c0 + c1)  { sDig = 2046 - i0; sRem = need - ex - c0; }
            __syncthreads();
            if (t == 0) { sPrefix = (unsigned)sDig; sNeed = sRem; }
        }
        __syncthreads();

        s_bins[i0] = 0; s_bins[i0 + 1] = 0;
        __syncthreads();
        {
            unsigned pfx = sPrefix;
            if ((e0v >> 21) == pfx) atomicAdd(&s_bins[(e0v >> 10) & 2047], 1);
            if ((e1v >> 21) == pfx) atomicAdd(&s_bins[(e1v >> 10) & 2047], 1);
            int c0, c1;
            __syncthreads();
            c0 = s_bins[2047 - i0]; c1 = s_bins[2046 - i0];
            int ex = scan_ex(c0 + c1, t, wsum);
            int need = sNeed;
            if (ex < need && need <= ex + c0)                 { sDig = 2047 - i0; sRem = need - ex; }
            else if (ex + c0 < need && need <= ex + c0 + c1)  { sDig = 2046 - i0; sRem = need - ex - c0; }
            __syncthreads();
            if (t == 0) { sPrefix = (sPrefix << 11) | (unsigned)sDig; sNeed = sRem; }
        }
        __syncthreads();

        s_bins[t] = 0;
        __syncthreads();
        {
            unsigned pfx = sPrefix;
            if ((e0v >> 10) == pfx) atomicAdd(&s_bins[e0v & 1023], 1);
            if ((e1v >> 10) == pfx) atomicAdd(&s_bins[e1v & 1023], 1);
            int c;
            __syncthreads();
            c = s_bins[1023 - t];
            int ex = scan_ex(c, t, wsum);
            int need = sNeed;
            if (ex < need && need <= ex + c) { sDig = 1023 - t; sRem = need - ex; }
            __syncthreads();
            if (t == 0) { sPrefix = (sPrefix << 10) | (unsigned)sDig; sNeed = sRem; }
        }
        __syncthreads();

        unsigned KT = sPrefix;
        int tneed = sNeed;
        int ng = KK - tneed;
        int pg[2], pt[2];
        pg[0] = (e0v > KT) ? 1 : 0;  pt[0] = (e0v == KT) ? 1 : 0;
        pg[1] = (e1v > KT) ? 1 : 0;  pt[1] = (e1v == KT) ? 1 : 0;
        int exg = scan_ex(pg[0] + pg[1], t, wsum);
        int ext = scan_ex(pt[0] + pt[1], t, wsum);
#pragma unroll
        for (int q = 0; q < 2; q++) {
            int i = i0 + q;
            int slot = -1;
            if (pg[q]) slot = exg;
            else if (pt[q] && ext < tneed) slot = ng + ext;
            if (slot >= 0) { s_perm[slot] = i; s_new[i] = slot; }
            else s_new[i] = -1;
            exg += pg[q];
            ext += pt[q];
        }
    }
    __syncthreads();

    // ---- gates for owned pooled nodes (dinv region dead) ----
    if (t < KK) {
        int node = s_perm[t];
        if ((node >> 10) == (int)rank) s_gate[t] = tanhf(s_scr[node]);
    }
    __syncthreads();

    // ---- P8: pooled precompute for OWNED (node,head) units ----
    {
        float hg[2][CC], as2[2], ad2[2];
        bool act[2] = {false, false};
#pragma unroll
        for (int pass = 0; pass < 2; pass++) {
            int u = t + pass * T;
            if (u >= KK * HH) break;
            int j = u / 3, h = u - 3 * j;
            int node = s_perm[j];
            if ((node >> 10) != (int)rank) continue;
            act[pass] = true;
            float gate = s_gate[j];
            float xp[10];
#pragma unroll
            for (int c = 0; c < 10; c++) xp[c] = s_hx[node * 12 + c] * gate;
            float as = 0.f, ad = 0.f;
#pragma unroll
            for (int c = 0; c < CC; c++) {
                int k = h * CC + c;
                float v = 0.f;
#pragma unroll
                for (int q = 0; q < 10; q++) v += xp[q] * Wgs[q * 60 + k];
                hg[pass][c] = v;
                as += v * asr[k];
                ad += v * ads[k];
            }
            as2[pass] = as; ad2[pass] = ad;
        }
        __syncthreads();   // all local x1/scr reads done
#pragma unroll
        for (int pass = 0; pass < 2; pass++) {
            int u = t + pass * T;
            if (u >= KK * HH || !act[pass]) continue;
            int j = u / 3, h = u - 3 * j;
#pragma unroll
            for (int c = 0; c < CC; c++) s_hG[j * 64 + h * CC + c] = hg[pass][c];
            s_als[u] = as2[pass];
            s_ald[u] = ad2[pass];
        }
    }
    CLUSTER_SYNC();     // peer hG rows + als/ald entries final

    // ---- P8b: copy peer-owned als/ald entries ----
#pragma unroll
    for (int pass = 0; pass < 2; pass++) {
        int u = t + pass * T;
        if (u >= KK * HH) break;
        int j = u / 3;
        if ((s_perm[j] >> 10) != (int)peer) continue;
        s_als[u] = ldc_f32(mapa_u32(s2u(&s_als[u]), peer));
        s_ald[u] = ldc_f32(mapa_u32(s2u(&s_ald[u]), peer));
    }
    __syncthreads();

    // ---- P9: GAT softmax-aggregate for owned units (remote hG via DSMEM) ----
    // logits ~1e-2: exp without max-subtraction is exact softmax.
    {
        float acc[2][CC];
        bool act[2] = {false, false};
#pragma unroll
        for (int pass = 0; pass < 2; pass++) {
            int u = t + pass * T;
            if (u >= KK * HH) break;
            int j = u / 3, h = u - 3 * j;
            int node = s_perm[j];
            if ((node >> 10) != (int)rank) continue;
            act[pass] = true;
            float aldj = s_ald[u];
            float w = __expf(lrelu(s_als[u] + aldj));
            float den = w;
#pragma unroll
            for (int c = 0; c < CC; c++) acc[pass][c] = s_hG[j * 64 + h * CC + c] * w;
            int nl = node & (NH - 1);
            int e0 = s_off[nl], e1 = e0 + s_cnt[nl];
            for (int e = e0; e < e1; e++) {
                int sj = s_new[s_csr[e]];
                if (sj < 0) continue;
                float ww = __expf(lrelu(s_als[sj * 3 + h] + aldj));
                den += ww;
                if ((s_perm[sj] >> 10) == (int)rank) {
                    const float* row = &s_hG[sj * 64 + h * CC];
#pragma unroll
                    for (int c = 0; c < CC; c++) acc[pass][c] += row[c] * ww;
                } else {
                    uint32_t ra = mapa_u32(s2u(&s_hG[sj * 64 + h * CC]), peer);
#pragma unroll
                    for (int c4 = 0; c4 < 5; c4++) {
                        float4 v = ldc_f4(ra + c4 * 16);
                        acc[pass][c4 * 4 + 0] += v.x * ww;
                        acc[pass][c4 * 4 + 1] += v.y * ww;
                        acc[pass][c4 * 4 + 2] += v.z * ww;
                        acc[pass][c4 * 4 + 3] += v.w * ww;
                    }
                }
            }
            float inv = 1.f / den;
#pragma unroll
            for (int c = 0; c < CC; c++) acc[pass][c] *= inv;
        }
        CLUSTER_SYNC();   // all hG reads (local + remote) complete cluster-wide
#pragma unroll
        for (int pass = 0; pass < 2; pass++) {
            int u = t + pass * T;
            if (u >= KK * HH || !act[pass]) continue;
            int j = u / 3, h = u - 3 * j;
#pragma unroll
            for (int c = 0; c < CC; c++) s_hG[j * 64 + h * CC + c] = acc[pass][c];
        }
    }
    __syncthreads();

    // ---- readout: sum OWNED pooled rows -> partial 60-vector ----
    {
        int col = t & 63, grp = t >> 6;       // 16 groups of 64
        if (col < 60) {                        // FIX: store guarded (r12 bug)
            float a = 0.f;
            for (int r = grp; r < KK; r += 16)
                if ((s_perm[r] >> 10) == (int)rank) a += s_hG[r * 64 + col];
            s_part[grp * 60 + col] = a;
        }
    }
    __syncthreads();
    if (t < 60) {
        float a = 0.f;
#pragma unroll
        for (int q = 0; q < 16; q++) a += s_part[q * 60 + t];
        s_gsum[t] = a;
    }
    CLUSTER_SYNC();     // both partials ready

    // ---- rank 0: combine + MLP + log_softmax + write out ----
    if (rank == 0) {
        if (t < 60)
            s_gsum[t] += ldc_f32(mapa_u32(s2u(&s_gsum[t]), 1u)) + (float)KK * bg[t];
        __syncthreads();
        if (t < 30) {
            float v = bf1[t];
#pragma unroll
            for (int c = 0; c < 60; c++) v += s_gsum[c] * Wf1[c * 30 + t];
            s_hb[t] = v > 0.f ? v : 0.f;
        }
        __syncthreads();
        if (t < 3) {
            float v = bf2[t];
#pragma unroll
            for (int c = 0; c < 30; c++) v += s_hb[c] * Wf2[c * 3 + t];
            s_zb[t] = v;
        }
        __syncthreads();
        if (t == 0) {
            float m = fmaxf(s_zb[0], fmaxf(s_zb[1], s_zb[2]));
            float lse = logf(expf(s_zb[0] - m) + expf(s_zb[1] - m) + expf(s_zb[2] - m)) + m;
            out[g * 3 + 0] = s_zb[0] - lse;
            out[g * 3 + 1] = s_zb[1] - lse;
            out[g * 3 + 2] = s_zb[2] - lse;
        }
    }
    CLUSTER_SYNC();     // keep peer smem alive until rank 0 is done
}

// ---------------- launch -----------------------------------------------------
extern "C" void kernel_launch(void* const* d_in, const int* in_sizes, int n_in,
                              void* d_out, int out_size) {
    const float* x     = (const float*)d_in[0];
    const int*   src   = (const int*)d_in[1];
    const int*   dst   = (const int*)d_in[2];
    const float* W1    = (const float*)d_in[4];
    const float* b1    = (const float*)d_in[5];
    const float* Ws    = (const float*)d_in[6];
    const float* bs    = (const float*)d_in[7];
    const float* Wg    = (const float*)d_in[8];
    const float* a_src = (const float*)d_in[9];
    const float* a_dst = (const float*)d_in[10];
    const float* bg    = (const float*)d_in[11];
    const float* Wf1   = (const float*)d_in[12];
    const float* bf1   = (const float*)d_in[13];
    const float* Wf2   = (const float*)d_in[14];
    const float* bf2   = (const float*)d_in[15];
    float* out = (float*)d_out;

    static int attr_set = 0;
    if (!attr_set) {
        cudaFuncSetAttribute(k_mega, cudaFuncAttributeMaxDynamicSharedMemorySize,
                             SMEM_TOTAL);
        attr_set = 1;
    }
    k_mega<<<NGR * 2, T, SMEM_TOTAL>>>(x, src, dst, W1, b1, Ws, bs, Wg,
                                       a_src, a_dst, bg, Wf1, bf1, Wf2, bf2, out);
}